// round 1
// baseline (speedup 1.0000x reference)
#include <cuda_runtime.h>
#include <cuda_bf16.h>
#include <math.h>

// Problem constants
#define NN      50000
#define NE      800000
#define F0      64
#define F1      128
#define F2      32
#define SCAN_B  1024
#define NBLK    ((NN + SCAN_B - 1) / SCAN_B)   // 49

// ---------------- scratch (static device globals; no allocation) -------------
__device__ float g_h1[NN * F1];     // x @ W1
__device__ float g_a1[NN * F1];     // relu(agg1 + b1)
__device__ float g_h2[NN * F2];     // a1 @ W2
__device__ float g_dinv[NN];
__device__ int   g_cnt[NN];
__device__ int   g_fill[NN];
__device__ int   g_rowptr[NN + 1];
__device__ int   g_blksum[64];
__device__ int   g_colsrc[NE];

// ---------------- CSR build --------------------------------------------------
__global__ void k_init() {
    int i = blockIdx.x * blockDim.x + threadIdx.x;
    if (i < NN) { g_cnt[i] = 0; g_fill[i] = 0; }
}

__global__ void k_count(const int* __restrict__ dst) {
    int e = blockIdx.x * blockDim.x + threadIdx.x;
    if (e < NE) atomicAdd(&g_cnt[dst[e]], 1);
}

__global__ void k_dinv() {
    int i = blockIdx.x * blockDim.x + threadIdx.x;
    if (i < NN) g_dinv[i] = rsqrtf((float)(g_cnt[i] + 1));   // +1 self loop
}

__global__ void k_scan1() {
    __shared__ int s[SCAN_B];
    int tid = threadIdx.x;
    int i = blockIdx.x * SCAN_B + tid;
    int v = (i < NN) ? g_cnt[i] : 0;
    s[tid] = v;
    __syncthreads();
    #pragma unroll
    for (int off = 1; off < SCAN_B; off <<= 1) {
        int t = (tid >= off) ? s[tid - off] : 0;
        __syncthreads();
        s[tid] += t;
        __syncthreads();
    }
    if (i < NN) g_rowptr[i] = s[tid] - v;          // exclusive within block
    if (tid == SCAN_B - 1) g_blksum[blockIdx.x] = s[tid];
}

__global__ void k_scan2() {
    if (threadIdx.x == 0) {
        int acc = 0;
        for (int i = 0; i < NBLK; i++) {
            int v = g_blksum[i];
            g_blksum[i] = acc;
            acc += v;
        }
    }
}

__global__ void k_scan3() {
    int i = blockIdx.x * blockDim.x + threadIdx.x;
    if (i < NN) g_rowptr[i] += g_blksum[i >> 10];
    if (i == 0) g_rowptr[NN] = NE;
}

__global__ void k_scatter(const int* __restrict__ src, const int* __restrict__ dst) {
    int e = blockIdx.x * blockDim.x + threadIdx.x;
    if (e < NE) {
        int d = dst[e];
        int pos = g_rowptr[d] + atomicAdd(&g_fill[d], 1);
        g_colsrc[pos] = src[e];
    }
}

// ---------------- GEMM 1: h1 = x @ W1   (N x 64 @ 64 x 128) ------------------
#define G1_NODES 16
__global__ void k_gemm1(const float* __restrict__ x, const float* __restrict__ W1) {
    __shared__ float sW[F0 * F1];        // 32 KB
    __shared__ float sX[G1_NODES * F0];  // 4 KB
    int tid = threadIdx.x;               // 128 threads = output column
    int n0 = blockIdx.x * G1_NODES;

    for (int i = tid; i < F0 * F1; i += 128) sW[i] = W1[i];
    for (int i = tid; i < G1_NODES * F0; i += 128) {
        int n = i / F0, k = i % F0;
        sX[i] = (n0 + n < NN) ? x[(n0 + n) * F0 + k] : 0.f;
    }
    __syncthreads();

    float acc[G1_NODES];
    #pragma unroll
    for (int j = 0; j < G1_NODES; j++) acc[j] = 0.f;

    #pragma unroll
    for (int k = 0; k < F0; k++) {
        float w = sW[k * F1 + tid];
        #pragma unroll
        for (int j = 0; j < G1_NODES; j++) acc[j] = fmaf(sX[j * F0 + k], w, acc[j]);
    }
    #pragma unroll
    for (int j = 0; j < G1_NODES; j++)
        if (n0 + j < NN) g_h1[(n0 + j) * F1 + tid] = acc[j];
}

// ---------------- Aggregation 1 (F=128, warp per node, float4) --------------
__global__ void k_agg1(const float* __restrict__ b1) {
    int gtid = blockIdx.x * blockDim.x + threadIdx.x;
    int n = gtid >> 5;
    int lane = gtid & 31;
    if (n >= NN) return;

    const float4* H = (const float4*)g_h1;      // row = 32 float4
    float dn = g_dinv[n];
    float4 h = H[n * 32 + lane];
    float4 acc;
    acc.x = dn * h.x; acc.y = dn * h.y; acc.z = dn * h.z; acc.w = dn * h.w;

    int e = g_rowptr[n], end = g_rowptr[n + 1];
    for (; e + 3 < end; e += 4) {
        int s0 = g_colsrc[e], s1 = g_colsrc[e + 1], s2 = g_colsrc[e + 2], s3 = g_colsrc[e + 3];
        float d0 = g_dinv[s0], d1 = g_dinv[s1], d2 = g_dinv[s2], d3 = g_dinv[s3];
        float4 v0 = H[s0 * 32 + lane], v1 = H[s1 * 32 + lane];
        float4 v2 = H[s2 * 32 + lane], v3 = H[s3 * 32 + lane];
        acc.x += d0 * v0.x + d1 * v1.x + d2 * v2.x + d3 * v3.x;
        acc.y += d0 * v0.y + d1 * v1.y + d2 * v2.y + d3 * v3.y;
        acc.z += d0 * v0.z + d1 * v1.z + d2 * v2.z + d3 * v3.z;
        acc.w += d0 * v0.w + d1 * v1.w + d2 * v2.w + d3 * v3.w;
    }
    for (; e < end; e++) {
        int s = g_colsrc[e];
        float d = g_dinv[s];
        float4 v = H[s * 32 + lane];
        acc.x += d * v.x; acc.y += d * v.y; acc.z += d * v.z; acc.w += d * v.w;
    }

    const float4* B = (const float4*)b1;
    float4 b = B[lane];
    float4 r;
    r.x = fmaxf(dn * acc.x + b.x, 0.f);
    r.y = fmaxf(dn * acc.y + b.y, 0.f);
    r.z = fmaxf(dn * acc.z + b.z, 0.f);
    r.w = fmaxf(dn * acc.w + b.w, 0.f);
    ((float4*)g_a1)[n * 32 + lane] = r;
}

// ---------------- GEMM 2: h2 = a1 @ W2  (N x 128 @ 128 x 32) ----------------
#define G2_NODES 32
__global__ void k_gemm2(const float* __restrict__ W2) {
    __shared__ float sW[F1 * F2];          // 16 KB
    __shared__ float sA[G2_NODES * F1];    // 16 KB
    int tid = threadIdx.x;                 // 128 threads
    int col = tid & 31;
    int sub = tid >> 5;                    // 0..3
    int n0 = blockIdx.x * G2_NODES;

    for (int i = tid; i < F1 * F2; i += 128) sW[i] = W2[i];
    for (int i = tid; i < G2_NODES * F1; i += 128) {
        int n = i / F1, k = i % F1;
        sA[i] = (n0 + n < NN) ? g_a1[(n0 + n) * F1 + k] : 0.f;
    }
    __syncthreads();

    float acc[8];
    #pragma unroll
    for (int j = 0; j < 8; j++) acc[j] = 0.f;

    for (int k = 0; k < F1; k++) {
        float w = sW[k * F2 + col];
        #pragma unroll
        for (int j = 0; j < 8; j++)
            acc[j] = fmaf(sA[(sub * 8 + j) * F1 + k], w, acc[j]);
    }
    #pragma unroll
    for (int j = 0; j < 8; j++) {
        int n = n0 + sub * 8 + j;
        if (n < NN) g_h2[n * F2 + col] = acc[j];
    }
}

// ---------------- Aggregation 2 (F=32, warp per node, scalar) ---------------
__global__ void k_agg2(const float* __restrict__ b2, float* __restrict__ hout) {
    int gtid = blockIdx.x * blockDim.x + threadIdx.x;
    int n = gtid >> 5;
    int lane = gtid & 31;
    if (n >= NN) return;

    float dn = g_dinv[n];
    float acc = dn * g_h2[n * F2 + lane];

    int e = g_rowptr[n], end = g_rowptr[n + 1];
    for (; e + 3 < end; e += 4) {
        int s0 = g_colsrc[e], s1 = g_colsrc[e + 1], s2 = g_colsrc[e + 2], s3 = g_colsrc[e + 3];
        float d0 = g_dinv[s0], d1 = g_dinv[s1], d2 = g_dinv[s2], d3 = g_dinv[s3];
        acc += d0 * g_h2[s0 * F2 + lane] + d1 * g_h2[s1 * F2 + lane]
             + d2 * g_h2[s2 * F2 + lane] + d3 * g_h2[s3 * F2 + lane];
    }
    for (; e < end; e++) {
        int s = g_colsrc[e];
        acc += g_dinv[s] * g_h2[s * F2 + lane];
    }
    hout[n * F2 + lane] = dn * acc + b2[lane];
}

// ---------------- GEMM 3: out = h @ Wc + bc  (N x 32 @ 32 x 32) -------------
#define G3_NODES 32
__global__ void k_gemm3(const float* __restrict__ h, const float* __restrict__ Wc,
                        const float* __restrict__ bc, float* __restrict__ out) {
    __shared__ float sW[F2 * F2];          // 4 KB
    __shared__ float sH[G3_NODES * F2];    // 4 KB
    int tid = threadIdx.x;                 // 128 threads
    int col = tid & 31;
    int sub = tid >> 5;
    int n0 = blockIdx.x * G3_NODES;

    for (int i = tid; i < F2 * F2; i += 128) sW[i] = Wc[i];
    for (int i = tid; i < G3_NODES * F2; i += 128) {
        int n = i / F2, k = i % F2;
        sH[i] = (n0 + n < NN) ? h[(n0 + n) * F2 + k] : 0.f;
    }
    __syncthreads();

    float bcv = bc[col];
    float acc[8];
    #pragma unroll
    for (int j = 0; j < 8; j++) acc[j] = 0.f;

    #pragma unroll
    for (int k = 0; k < F2; k++) {
        float w = sW[k * F2 + col];
        #pragma unroll
        for (int j = 0; j < 8; j++)
            acc[j] = fmaf(sH[(sub * 8 + j) * F2 + k], w, acc[j]);
    }
    #pragma unroll
    for (int j = 0; j < 8; j++) {
        int n = n0 + sub * 8 + j;
        if (n < NN) out[n * F2 + col] = acc[j] + bcv;
    }
}

// ---------------- launch -----------------------------------------------------
extern "C" void kernel_launch(void* const* d_in, const int* in_sizes, int n_in,
                              void* d_out, int out_size) {
    const float* x   = (const float*)d_in[0];
    const int*   ei  = (const int*)d_in[1];     // [2, NE] int32
    const float* W1  = (const float*)d_in[2];
    const float* b1  = (const float*)d_in[3];
    const float* W2  = (const float*)d_in[4];
    const float* b2  = (const float*)d_in[5];
    const float* Wc  = (const float*)d_in[6];
    const float* bc  = (const float*)d_in[7];

    const int* src = ei;
    const int* dst = ei + NE;

    float* out  = (float*)d_out;            // [NN, F2]
    float* hout = (float*)d_out + NN * F2;  // [NN, F2]  (second tuple element)

    int nb_nodes = (NN + 255) / 256;
    int nb_edges = (NE + 255) / 256;

    // CSR build
    k_init<<<nb_nodes, 256>>>();
    k_count<<<nb_edges, 256>>>(dst);
    k_dinv<<<nb_nodes, 256>>>();
    k_scan1<<<NBLK, SCAN_B>>>();
    k_scan2<<<1, 32>>>();
    k_scan3<<<nb_nodes, 256>>>();
    k_scatter<<<nb_edges, 256>>>(src, dst);

    // Layer 1
    k_gemm1<<<(NN + G1_NODES - 1) / G1_NODES, 128>>>(x, W1);
    k_agg1<<<(NN * 32 + 255) / 256, 256>>>(b1);

    // Layer 2
    k_gemm2<<<(NN + G2_NODES - 1) / G2_NODES, 128>>>(W2);
    k_agg2<<<(NN * 32 + 255) / 256, 256>>>(b2, hout);

    // Classifier
    k_gemm3<<<(NN + G3_NODES - 1) / G3_NODES, 128>>>(hout, Wc, bc, out);
}

// round 4
// speedup vs baseline: 1.1546x; 1.1546x over previous
#include <cuda_runtime.h>
#include <cuda_bf16.h>
#include <math.h>

#define NN      50000
#define NE      800000
#define F0      64
#define F1      128
#define F2      32
#define SCAN_B  1024
#define NBLK    ((NN + SCAN_B - 1) / SCAN_B)   // 49

// ---------------- scratch (static device globals) ----------------------------
__device__ float g_ax[NN * F0];     // aggregated x
__device__ float g_a1[NN * F1];     // relu(agg(x) @ W1 + b1)
__device__ float g_h2[NN * F2];     // a1 @ W2
__device__ float g_dinv[NN];
__device__ int   g_cnt[NN];
__device__ int   g_fill[NN];
__device__ int   g_rowptr[NN + 1];
__device__ int   g_blksum[64];
__device__ int   g_colsrc[NE];

// ---------------- CSR build --------------------------------------------------
__global__ void k_init() {
    int i = blockIdx.x * blockDim.x + threadIdx.x;
    if (i < NN) g_cnt[i] = 0;
}

__global__ void k_count(const int* __restrict__ dst) {
    int e = blockIdx.x * blockDim.x + threadIdx.x;
    if (e < NE) atomicAdd(&g_cnt[dst[e]], 1);
}

__global__ void k_scan1() {
    __shared__ int s[SCAN_B];
    int tid = threadIdx.x;
    int i = blockIdx.x * SCAN_B + tid;
    int v = (i < NN) ? g_cnt[i] : 0;
    if (i < NN) g_dinv[i] = rsqrtf((float)(v + 1));   // +1 self loop
    s[tid] = v;
    __syncthreads();
    #pragma unroll
    for (int off = 1; off < SCAN_B; off <<= 1) {
        int t = (tid >= off) ? s[tid - off] : 0;
        __syncthreads();
        s[tid] += t;
        __syncthreads();
    }
    if (i < NN) g_rowptr[i] = s[tid] - v;
    if (tid == SCAN_B - 1) g_blksum[blockIdx.x] = s[tid];
}

__global__ void k_scan2() {
    if (threadIdx.x == 0) {
        int acc = 0;
        for (int i = 0; i < NBLK; i++) {
            int v = g_blksum[i];
            g_blksum[i] = acc;
            acc += v;
        }
    }
}

__global__ void k_scan3() {
    int i = blockIdx.x * blockDim.x + threadIdx.x;
    if (i < NN) {
        int r = g_rowptr[i] + g_blksum[i >> 10];
        g_rowptr[i] = r;
        g_fill[i] = r;
    }
    if (i == 0) g_rowptr[NN] = NE;
}

__global__ void k_scatter(const int* __restrict__ src, const int* __restrict__ dst) {
    int e = blockIdx.x * blockDim.x + threadIdx.x;
    if (e < NE) {
        int pos = atomicAdd(&g_fill[dst[e]], 1);
        g_colsrc[pos] = src[e];
    }
}

// ---------------- Aggregate x (F=64, warp per node, float2 per lane) ---------
__global__ void __launch_bounds__(256) k_aggx(const float* __restrict__ x) {
    int gtid = blockIdx.x * blockDim.x + threadIdx.x;
    int n = gtid >> 5;
    int lane = gtid & 31;
    if (n >= NN) return;

    const float2* X = (const float2*)x;     // row = 32 float2
    float dn = g_dinv[n];
    float2 s = X[n * 32 + lane];
    float ax = dn * s.x, ay = dn * s.y;

    int e = g_rowptr[n], end = g_rowptr[n + 1];
    for (; e + 3 < end; e += 4) {
        int s0 = g_colsrc[e], s1 = g_colsrc[e + 1], s2 = g_colsrc[e + 2], s3 = g_colsrc[e + 3];
        float d0 = g_dinv[s0], d1 = g_dinv[s1], d2 = g_dinv[s2], d3 = g_dinv[s3];
        float2 v0 = X[s0 * 32 + lane], v1 = X[s1 * 32 + lane];
        float2 v2 = X[s2 * 32 + lane], v3 = X[s3 * 32 + lane];
        ax += d0 * v0.x + d1 * v1.x + d2 * v2.x + d3 * v3.x;
        ay += d0 * v0.y + d1 * v1.y + d2 * v2.y + d3 * v3.y;
    }
    for (; e < end; e++) {
        int sc = g_colsrc[e];
        float d = g_dinv[sc];
        float2 v = X[sc * 32 + lane];
        ax += d * v.x; ay += d * v.y;
    }
    float2 o; o.x = dn * ax; o.y = dn * ay;
    ((float2*)g_ax)[n * 32 + lane] = o;
}

// ---------------- GEMM1: a1 = relu(agg_x @ W1 + b1)  (N x 64 @ 64 x 128) ----
// 128 threads, 32 nodes/block; each thread: 4 nodes x 8 cols register tile.
__global__ void __launch_bounds__(128) k_gemm1(const float* __restrict__ W1,
                                               const float* __restrict__ b1) {
    __shared__ float sW[F0 * F1];        // 32 KB, row k contiguous (128)
    __shared__ float sA[F0 * 36];        // 9 KB, k-major, padded to 36
    int tid = threadIdx.x;
    int n0 = blockIdx.x * 32;

    {
        const float4* Wp = (const float4*)W1;
        float4* Sp = (float4*)sW;
        #pragma unroll
        for (int i = tid; i < F0 * F1 / 4; i += 128) Sp[i] = Wp[i];
    }
    for (int idx = tid; idx < 32 * F0; idx += 128) {
        int j = idx >> 6, k = idx & 63;
        sA[k * 36 + j] = (n0 + j < NN) ? g_ax[(n0 + j) * F0 + k] : 0.f;
    }
    __syncthreads();

    int cg = tid & 15, jg = tid >> 4;    // 16 col-groups x 8 node-groups
    int c0 = cg * 8, j0 = jg * 4;

    float acc[4][8];
    #pragma unroll
    for (int a = 0; a < 4; a++)
        #pragma unroll
        for (int b = 0; b < 8; b++) acc[a][b] = 0.f;

    #pragma unroll 4
    for (int k = 0; k < F0; k++) {
        float4 w0 = *(const float4*)&sW[k * F1 + c0];
        float4 w1 = *(const float4*)&sW[k * F1 + c0 + 4];
        float4 av = *(const float4*)&sA[k * 36 + j0];
        float a0 = av.x, a1 = av.y, a2 = av.z, a3 = av.w;
        acc[0][0] = fmaf(a0, w0.x, acc[0][0]); acc[0][1] = fmaf(a0, w0.y, acc[0][1]);
        acc[0][2] = fmaf(a0, w0.z, acc[0][2]); acc[0][3] = fmaf(a0, w0.w, acc[0][3]);
        acc[0][4] = fmaf(a0, w1.x, acc[0][4]); acc[0][5] = fmaf(a0, w1.y, acc[0][5]);
        acc[0][6] = fmaf(a0, w1.z, acc[0][6]); acc[0][7] = fmaf(a0, w1.w, acc[0][7]);
        acc[1][0] = fmaf(a1, w0.x, acc[1][0]); acc[1][1] = fmaf(a1, w0.y, acc[1][1]);
        acc[1][2] = fmaf(a1, w0.z, acc[1][2]); acc[1][3] = fmaf(a1, w0.w, acc[1][3]);
        acc[1][4] = fmaf(a1, w1.x, acc[1][4]); acc[1][5] = fmaf(a1, w1.y, acc[1][5]);
        acc[1][6] = fmaf(a1, w1.z, acc[1][6]); acc[1][7] = fmaf(a1, w1.w, acc[1][7]);
        acc[2][0] = fmaf(a2, w0.x, acc[2][0]); acc[2][1] = fmaf(a2, w0.y, acc[2][1]);
        acc[2][2] = fmaf(a2, w0.z, acc[2][2]); acc[2][3] = fmaf(a2, w0.w, acc[2][3]);
        acc[2][4] = fmaf(a2, w1.x, acc[2][4]); acc[2][5] = fmaf(a2, w1.y, acc[2][5]);
        acc[2][6] = fmaf(a2, w1.z, acc[2][6]); acc[2][7] = fmaf(a2, w1.w, acc[2][7]);
        acc[3][0] = fmaf(a3, w0.x, acc[3][0]); acc[3][1] = fmaf(a3, w0.y, acc[3][1]);
        acc[3][2] = fmaf(a3, w0.z, acc[3][2]); acc[3][3] = fmaf(a3, w0.w, acc[3][3]);
        acc[3][4] = fmaf(a3, w1.x, acc[3][4]); acc[3][5] = fmaf(a3, w1.y, acc[3][5]);
        acc[3][6] = fmaf(a3, w1.z, acc[3][6]); acc[3][7] = fmaf(a3, w1.w, acc[3][7]);
    }

    float bl[8];
    #pragma unroll
    for (int i = 0; i < 8; i++) bl[i] = __ldg(&b1[c0 + i]);

    #pragma unroll
    for (int jj = 0; jj < 4; jj++) {
        int n = n0 + j0 + jj;
        if (n < NN) {
            float4 r0, r1;
            r0.x = fmaxf(acc[jj][0] + bl[0], 0.f);
            r0.y = fmaxf(acc[jj][1] + bl[1], 0.f);
            r0.z = fmaxf(acc[jj][2] + bl[2], 0.f);
            r0.w = fmaxf(acc[jj][3] + bl[3], 0.f);
            r1.x = fmaxf(acc[jj][4] + bl[4], 0.f);
            r1.y = fmaxf(acc[jj][5] + bl[5], 0.f);
            r1.z = fmaxf(acc[jj][6] + bl[6], 0.f);
            r1.w = fmaxf(acc[jj][7] + bl[7], 0.f);
            *(float4*)&g_a1[n * F1 + c0]     = r0;
            *(float4*)&g_a1[n * F1 + c0 + 4] = r1;
        }
    }
}

// ---------------- GEMM2: h2 = a1 @ W2  (N x 128 @ 128 x 32) -----------------
// 128 threads, 32 nodes/block; each thread: 8 nodes x 4 cols register tile.
__global__ void __launch_bounds__(128) k_gemm2(const float* __restrict__ W2) {
    __shared__ float sW[F1 * F2];        // 16 KB
    __shared__ float sA[F1 * 36];        // 18 KB
    int tid = threadIdx.x;
    int n0 = blockIdx.x * 32;

    {
        const float4* Wp = (const float4*)W2;
        float4* Sp = (float4*)sW;
        #pragma unroll
        for (int i = tid; i < F1 * F2 / 4; i += 128) Sp[i] = Wp[i];
    }
    for (int idx = tid; idx < 32 * F1; idx += 128) {
        int j = idx >> 7, k = idx & 127;
        sA[k * 36 + j] = (n0 + j < NN) ? g_a1[(n0 + j) * F1 + k] : 0.f;
    }
    __syncthreads();

    int cg = tid & 7, jg = tid >> 3;     // 8 col-groups x 16 node-groups
    int c0 = cg * 4, j0 = jg * 2;

    float acc[2][4];
    #pragma unroll
    for (int a = 0; a < 2; a++)
        #pragma unroll
        for (int b = 0; b < 4; b++) acc[a][b] = 0.f;

    #pragma unroll 8
    for (int k = 0; k < F1; k++) {
        float4 w = *(const float4*)&sW[k * F2 + c0];
        float2 av = *(const float2*)&sA[k * 36 + j0];
        acc[0][0] = fmaf(av.x, w.x, acc[0][0]);
        acc[0][1] = fmaf(av.x, w.y, acc[0][1]);
        acc[0][2] = fmaf(av.x, w.z, acc[0][2]);
        acc[0][3] = fmaf(av.x, w.w, acc[0][3]);
        acc[1][0] = fmaf(av.y, w.x, acc[1][0]);
        acc[1][1] = fmaf(av.y, w.y, acc[1][1]);
        acc[1][2] = fmaf(av.y, w.z, acc[1][2]);
        acc[1][3] = fmaf(av.y, w.w, acc[1][3]);
    }

    #pragma unroll
    for (int jj = 0; jj < 2; jj++) {
        int n = n0 + j0 + jj;
        if (n < NN) {
            float4 r;
            r.x = acc[jj][0]; r.y = acc[jj][1]; r.z = acc[jj][2]; r.w = acc[jj][3];
            *(float4*)&g_h2[n * F2 + c0] = r;
        }
    }
}

// ---------------- Aggregation 2 (F=32, warp per node) -----------------------
__global__ void __launch_bounds__(256) k_agg2(const float* __restrict__ b2,
                                              float* __restrict__ hout) {
    int gtid = blockIdx.x * blockDim.x + threadIdx.x;
    int n = gtid >> 5;
    int lane = gtid & 31;
    if (n >= NN) return;

    float dn = g_dinv[n];
    float acc = dn * g_h2[n * F2 + lane];

    int e = g_rowptr[n], end = g_rowptr[n + 1];
    for (; e + 3 < end; e += 4) {
        int s0 = g_colsrc[e], s1 = g_colsrc[e + 1], s2 = g_colsrc[e + 2], s3 = g_colsrc[e + 3];
        float d0 = g_dinv[s0], d1 = g_dinv[s1], d2 = g_dinv[s2], d3 = g_dinv[s3];
        acc += d0 * g_h2[s0 * F2 + lane] + d1 * g_h2[s1 * F2 + lane]
             + d2 * g_h2[s2 * F2 + lane] + d3 * g_h2[s3 * F2 + lane];
    }
    for (; e < end; e++) {
        int s = g_colsrc[e];
        acc += g_dinv[s] * g_h2[s * F2 + lane];
    }
    hout[n * F2 + lane] = dn * acc + b2[lane];
}

// ---------------- GEMM3: out = h @ Wc + bc  (N x 32 @ 32 x 32) --------------
__global__ void __launch_bounds__(128) k_gemm3(const float* __restrict__ h,
                                               const float* __restrict__ Wc,
                                               const float* __restrict__ bc,
                                               float* __restrict__ out) {
    __shared__ float sW[F2 * F2];        // 4 KB
    __shared__ float sH[F2 * 36];        // 4.5 KB
    int tid = threadIdx.x;
    int n0 = blockIdx.x * 32;

    {
        const float4* Wp = (const float4*)Wc;
        float4* Sp = (float4*)sW;
        #pragma unroll
        for (int i = tid; i < F2 * F2 / 4; i += 128) Sp[i] = Wp[i];
    }
    for (int idx = tid; idx < 32 * F2; idx += 128) {
        int j = idx >> 5, k = idx & 31;
        sH[k * 36 + j] = (n0 + j < NN) ? h[(n0 + j) * F2 + k] : 0.f;
    }
    __syncthreads();

    int cg = tid & 7, jg = tid >> 3;
    int c0 = cg * 4, j0 = jg * 2;

    float acc[2][4];
    #pragma unroll
    for (int a = 0; a < 2; a++)
        #pragma unroll
        for (int b = 0; b < 4; b++) acc[a][b] = 0.f;

    #pragma unroll
    for (int k = 0; k < F2; k++) {
        float4 w = *(const float4*)&sW[k * F2 + c0];
        float2 av = *(const float2*)&sH[k * 36 + j0];
        acc[0][0] = fmaf(av.x, w.x, acc[0][0]);
        acc[0][1] = fmaf(av.x, w.y, acc[0][1]);
        acc[0][2] = fmaf(av.x, w.z, acc[0][2]);
        acc[0][3] = fmaf(av.x, w.w, acc[0][3]);
        acc[1][0] = fmaf(av.y, w.x, acc[1][0]);
        acc[1][1] = fmaf(av.y, w.y, acc[1][1]);
        acc[1][2] = fmaf(av.y, w.z, acc[1][2]);
        acc[1][3] = fmaf(av.y, w.w, acc[1][3]);
    }

    float b0 = __ldg(&bc[c0]), b1v = __ldg(&bc[c0 + 1]);
    float b2v = __ldg(&bc[c0 + 2]), b3 = __ldg(&bc[c0 + 3]);
    #pragma unroll
    for (int jj = 0; jj < 2; jj++) {
        int n = n0 + j0 + jj;
        if (n < NN) {
            float4 r;
            r.x = acc[jj][0] + b0; r.y = acc[jj][1] + b1v;
            r.z = acc[jj][2] + b2v; r.w = acc[jj][3] + b3;
            *(float4*)&out[n * F2 + c0] = r;
        }
    }
}

// ---------------- launch -----------------------------------------------------
extern "C" void kernel_launch(void* const* d_in, const int* in_sizes, int n_in,
                              void* d_out, int out_size) {
    const float* x   = (const float*)d_in[0];
    const int*   ei  = (const int*)d_in[1];
    const float* W1  = (const float*)d_in[2];
    const float* b1  = (const float*)d_in[3];
    const float* W2  = (const float*)d_in[4];
    const float* b2  = (const float*)d_in[5];
    const float* Wc  = (const float*)d_in[6];
    const float* bc  = (const float*)d_in[7];

    const int* src = ei;
    const int* dst = ei + NE;

    float* out  = (float*)d_out;            // [NN, F2]
    float* hout = (float*)d_out + NN * F2;  // [NN, F2]

    int nb_nodes = (NN + 255) / 256;
    int nb_edges = (NE + 255) / 256;
    int nb_gemm  = (NN + 31) / 32;

    // CSR build
    k_init<<<nb_nodes, 256>>>();
    k_count<<<nb_edges, 256>>>(dst);
    k_scan1<<<NBLK, SCAN_B>>>();
    k_scan2<<<1, 32>>>();
    k_scan3<<<nb_nodes, 256>>>();
    k_scatter<<<nb_edges, 256>>>(src, dst);

    // Layer 1 (reordered: aggregate x, then GEMM)
    k_aggx<<<(NN * 32 + 255) / 256, 256>>>(x);
    k_gemm1<<<nb_gemm, 128>>>(W1, b1);

    // Layer 2
    k_gemm2<<<nb_gemm, 128>>>(W2);
    k_agg2<<<(NN * 32 + 255) / 256, 256>>>(b2, hout);

    // Classifier
    k_gemm3<<<nb_gemm, 128>>>(hout, Wc, bc, out);
}